// round 16
// baseline (speedup 1.0000x reference)
#include <cuda_runtime.h>
#include <cuda_bf16.h>
#include <mma.h>
#include <cstdint>
#include <math.h>

#define NN 16384
#define LL 50
#define EE 64
#define CEDIM 128
#define NUSERS 100000
#define NRAT 6

typedef unsigned long long ull;
typedef unsigned int u32;

using namespace nvcuda;
typedef wmma::fragment<wmma::matrix_a, 16, 16, 16, __nv_bfloat16, wmma::row_major> FragA;
typedef wmma::fragment<wmma::matrix_b, 16, 16, 16, __nv_bfloat16, wmma::row_major> FragB;
typedef wmma::fragment<wmma::accumulator, 16, 16, 16, float> FragC;

// ---------------- device scratch ----------------
__device__ float g_post[NN * EE];                    // 4 MB
__device__ float g_post_a1[NN * EE];                 // 4 MB  (post @ A1b + bA1, fp32)
__device__ float g_o[(size_t)NN * LL * EE];          // 210 MB
__device__ float g_logits[NN * LL];                  // 3.3 MB
__device__ int   g_pairs[NN * LL];                   // 3.3 MB
__device__ int   g_count;
#define RBL 68
// packed hi/lo bf16 u table
__device__ __nv_bfloat16 g_u2e_h[NUSERS * EE];
__device__ __nv_bfloat16 g_u2e_l[NUSERS * EE];

__global__ void k_reset() { g_count = 0; }

__global__ void k_build_pairs(const int* __restrict__ lengths) {
    int n = blockIdx.x * blockDim.x + threadIdx.x;
    if (n >= NN) return;
    int len = lengths[n];
    int base = atomicAdd(&g_count, len);
    for (int l = 0; l < len; ++l) g_pairs[base + l] = (n << 6) | l;
}

__global__ void k_pack_emb(const float* __restrict__ u2e) {
    int i = blockIdx.x * blockDim.x + threadIdx.x;
    if (i < NUSERS * EE) {
        float x = u2e[i];
        __nv_bfloat16 h = __float2bfloat16(x);
        g_u2e_h[i] = h;
        g_u2e_l[i] = __float2bfloat16(x - __bfloat162float(h));
    }
}

// ---------------- helpers ----------------
__device__ __forceinline__ void ffma2(ull& d, ull a, ull b) {
    asm("fma.rn.f32x2 %0, %1, %2, %0;" : "+l"(d) : "l"(a), "l"(b));
}
__device__ __forceinline__ float hsum2(ull v) {
    float2 p = *(float2*)&v;
    return p.x + p.y;
}
__device__ __forceinline__ void cp16(void* dst, const void* src) {
    unsigned d = (unsigned)__cvta_generic_to_shared(dst);
    asm volatile("cp.async.cg.shared.global [%0], [%1], 16;" :: "r"(d), "l"(src));
}
__device__ __forceinline__ void cp_commit() {
    asm volatile("cp.async.commit_group;");
}
__device__ __forceinline__ void cp_wait0() {
    asm volatile("cp.async.wait_group 0;" ::: "memory");
}
__device__ __forceinline__ void cp_wait1() {
    asm volatile("cp.async.wait_group 1;" ::: "memory");
}
__device__ __forceinline__ void barh(int hf) {
    asm volatile("bar.sync %0, 256;" :: "r"(hf + 1) : "memory");
}
__device__ __forceinline__ u32 packbf(float x0, float x1) {
    u32 r;
    asm("cvt.rn.bf16x2.f32 %0, %1, %2;" : "=r"(r) : "f"(x1), "f"(x0));
    return r;
}

__device__ __forceinline__ void load_wt(const float* __restrict__ Wg, float* __restrict__ Wt,
                                        int K, int tid, int nthr) {
    for (int i = tid; i < K * 64; i += nthr) {
        int k = i >> 6, f = i & 63;
        Wt[(k >> 2) * 256 + ((f >> 2) + (f & 3) * 16) * 4 + (k & 3)] = Wg[i];
    }
}

#define MAP_SLOTS() \
    const int fslot = (((tid >> 5) & 3) << 2) + (tid & 3); \
    const int ibase = ((tid >> 7) << 5) + ((tid >> 2) & 7);

template<bool RELU>
__device__ __forceinline__ void tile_gemm_p(
    const float* __restrict__ Wt, const float* __restrict__ bias,
    const float* __restrict__ inA, int ldA, int K,
    float* __restrict__ out, int ldO, int tid)
{
    MAP_SLOTS();
    ull acc[4][4];
    #pragma unroll
    for (int j = 0; j < 4; ++j)
        #pragma unroll
        for (int ff = 0; ff < 4; ++ff) acc[j][ff] = 0ull;

    const float* wp = Wt + fslot * 4;
    const float* xp = inA + ibase * ldA;
    const int nkb = K >> 2;
    #pragma unroll 4
    for (int kb = 0; kb < nkb; ++kb) {
        ulonglong2 w[4];
        #pragma unroll
        for (int ff = 0; ff < 4; ++ff)
            w[ff] = *(const ulonglong2*)(wp + kb * 256 + ff * 64);
        ulonglong2 x[4];
        #pragma unroll
        for (int j = 0; j < 4; ++j)
            x[j] = *(const ulonglong2*)(xp + j * (8 * ldA) + kb * 4);
        #pragma unroll
        for (int j = 0; j < 4; ++j)
            #pragma unroll
            for (int ff = 0; ff < 4; ++ff) {
                ffma2(acc[j][ff], x[j].x, w[ff].x);
                ffma2(acc[j][ff], x[j].y, w[ff].y);
            }
    }
    float4 b4 = ((const float4*)bias)[fslot];
    #pragma unroll
    for (int j = 0; j < 4; ++j) {
        float4 v;
        v.x = hsum2(acc[j][0]) + b4.x;
        v.y = hsum2(acc[j][1]) + b4.y;
        v.z = hsum2(acc[j][2]) + b4.z;
        v.w = hsum2(acc[j][3]) + b4.w;
        if (RELU) {
            v.x = fmaxf(v.x, 0.f); v.y = fmaxf(v.y, 0.f);
            v.z = fmaxf(v.z, 0.f); v.w = fmaxf(v.w, 0.f);
        }
        *(float4*)(out + (ibase + 8 * j) * ldO + fslot * 4) = v;
    }
}

// ---------------- post kernel: post + post_a1 in one launch ----------------
#define LDIN 132

struct SmemPost {
    float Wet[128 * 64];
    float Wa1b[64 * 64];
    float bWe[64], bA1v[64];
    float in[64 * LDIN];
    float postb[64 * RBL];
    int   cix[64];
};

__global__ void __launch_bounds__(256, 1) k_post(
    const float* __restrict__ content, const float* __restrict__ Weg,
    const float* __restrict__ bWeg, const int* __restrict__ pr_content,
    const float* __restrict__ A1g, const float* __restrict__ bA1g)
{
    extern __shared__ float smem_raw[];
    SmemPost& s = *(SmemPost*)smem_raw;
    int tid = threadIdx.x;
    load_wt(Weg, s.Wet, 128, tid, 256);
    load_wt(A1g + 64 * 64, s.Wa1b, 64, tid, 256);
    if (tid < 64) {
        s.bWe[tid] = bWeg[tid]; s.bA1v[tid] = bA1g[tid];
        s.cix[tid] = pr_content[blockIdx.x * 64 + tid];
    }
    __syncthreads();
    for (int v = tid; v < 64 * 32; v += 256) {
        int it = v >> 5, sub = v & 31;
        cp16(s.in + it * LDIN + sub * 4,
             content + (size_t)s.cix[it] * 128 + sub * 4);
    }
    cp_commit(); cp_wait0();
    __syncthreads();
    // post -> smem (relu)
    tile_gemm_p<true>(s.Wet, s.bWe, s.in, LDIN, 128, s.postb, RBL, tid);
    __syncthreads();
    // write post to gmem
    for (int v = tid; v < 64 * 16; v += 256) {
        int it = v >> 4, sub = v & 15;
        ((float4*)(g_post + ((size_t)blockIdx.x * 64 + it) * 64))[sub] =
            *(const float4*)(s.postb + it * RBL + sub * 4);
    }
    // post_a1 = post @ A1b + bA1 (linear)
    tile_gemm_p<false>(s.Wa1b, s.bA1v, s.postb, RBL, 64,
                       g_post_a1 + (size_t)blockIdx.x * 64 * 64, 64, tid);
}

// ==================== WMMA main kernel: 512 threads, two 256-thread halves ====
#define PLD 72   // bf16 plane stride (144B)
#define SLD 68   // fp32 scratch stride (272B)

struct HalfW {
    __nv_bfloat16 pu[2][2][64 * PLD];   // [parity][hi/lo]
    float pstage[64 * RBL];             // post_a1 rows (fp32)
    float scratch[64 * SLD];
    int idx[2][4][64];                  // [buf][pn,pl,uix,rix]
};
struct SmemW {
    HalfW h[2];
    __nv_bfloat16 Wt[8][64 * PLD];      // {W1a,W2,A1a,A2} x {hi,lo}
    float rbias[NRAT * RBL];
    float cb[3 * 64];                   // b2 | bA2 | A3
};

__device__ __forceinline__ void build_w(const float* __restrict__ Wg,
                                        __nv_bfloat16* wh, __nv_bfloat16* wl, int tid) {
    for (int i = tid; i < 64 * 64; i += 512) {
        int k = i >> 6, f = i & 63;
        float w = Wg[k * 64 + f];
        __nv_bfloat16 h = __float2bfloat16(w);
        wh[k * PLD + f] = h;
        wl[k * PLD + f] = __float2bfloat16(w - __bfloat162float(h));
    }
}

// one 64-K MMA stage for a 16x64 warp band: acc[c] += [Ah|Al] x [Bh|Bl]
__device__ __forceinline__ void mma_stage_h(
    FragC acc[2],
    const __nv_bfloat16* Ah, const __nv_bfloat16* Al,
    const __nv_bfloat16* Bh, const __nv_bfloat16* Bl, int rw, int cw)
{
    #pragma unroll
    for (int kt = 0; kt < 4; ++kt) {
        FragA ah, al;
        wmma::load_matrix_sync(ah, Ah + (rw * 16) * PLD + kt * 16, PLD);
        wmma::load_matrix_sync(al, Al + (rw * 16) * PLD + kt * 16, PLD);
        #pragma unroll
        for (int c = 0; c < 2; ++c) {
            FragB bh, bl;
            wmma::load_matrix_sync(bh, Bh + kt * 16 * PLD + cw * 32 + c * 16, PLD);
            wmma::load_matrix_sync(bl, Bl + kt * 16 * PLD + cw * 32 + c * 16, PLD);
            wmma::mma_sync(acc[c], ah, bh, acc[c]);
            wmma::mma_sync(acc[c], al, bh, acc[c]);
            wmma::mma_sync(acc[c], ah, bl, acc[c]);
        }
    }
}

#define ZERO_ACC() do { \
    wmma::fill_fragment(acc[0], 0.f); \
    wmma::fill_fragment(acc[1], 0.f); \
} while (0)

// BM: 0 = column bias cb; 1 = row bias rbias[rix[m]]; 2 = row bias pstage[m]
template<int BM>
__device__ __forceinline__ void store_convert_h(
    HalfW& h, FragC acc[2], const float* __restrict__ bias_c,
    const int* __restrict__ rix,
    __nv_bfloat16* dh, __nv_bfloat16* dl,
    int rw, int cw, int htid, int hf,
    bool og, const int* __restrict__ pn, const int* __restrict__ pl)
{
    #pragma unroll
    for (int c = 0; c < 2; ++c)
        wmma::store_matrix_sync(h.scratch + (rw * 16) * SLD + cw * 32 + c * 16,
                                acc[c], SLD, wmma::mem_row_major);
    barh(hf);
    {
        int m = htid >> 2, c0 = (htid & 3) << 4;   // 4 threads/row, 16 cols each
        const float* src = h.scratch + m * SLD + c0;
        const float* bb;
        if (BM == 0)      bb = bias_c + c0;
        else if (BM == 1) bb = bias_c + rix[m] * RBL + c0;
        else              bb = bias_c + m * RBL + c0;
        float v[16];
        #pragma unroll
        for (int q = 0; q < 4; ++q) {
            float4 x = *(const float4*)(src + q * 4);
            float4 b = *(const float4*)(bb + q * 4);
            v[q * 4]     = fmaxf(x.x + b.x, 0.f);
            v[q * 4 + 1] = fmaxf(x.y + b.y, 0.f);
            v[q * 4 + 2] = fmaxf(x.z + b.z, 0.f);
            v[q * 4 + 3] = fmaxf(x.w + b.w, 0.f);
        }
        u32 hp[8], lp[8];
        #pragma unroll
        for (int e = 0; e < 8; ++e) {
            float x0 = v[2 * e], x1 = v[2 * e + 1];
            u32 hw = packbf(x0, x1);
            float h0 = __uint_as_float(hw << 16);
            float h1 = __uint_as_float(hw & 0xffff0000u);
            hp[e] = hw;
            lp[e] = packbf(x0 - h0, x1 - h1);
        }
        *(uint4*)(dh + m * PLD + c0)     = make_uint4(hp[0], hp[1], hp[2], hp[3]);
        *(uint4*)(dh + m * PLD + c0 + 8) = make_uint4(hp[4], hp[5], hp[6], hp[7]);
        *(uint4*)(dl + m * PLD + c0)     = make_uint4(lp[0], lp[1], lp[2], lp[3]);
        *(uint4*)(dl + m * PLD + c0 + 8) = make_uint4(lp[4], lp[5], lp[6], lp[7]);
        if (og) {
            float* orow = g_o + ((size_t)pn[m] * LL + pl[m]) * 64 + c0;
            #pragma unroll
            for (int q = 0; q < 4; ++q)
                *(float4*)(orow + q * 4) =
                    make_float4(v[q * 4], v[q * 4 + 1], v[q * 4 + 2], v[q * 4 + 3]);
        }
    }
    barh(hf);
}

__global__ void __launch_bounds__(512, 1) k_main_w(
    const float* __restrict__ W1g, const float* __restrict__ W2g,
    const float* __restrict__ A1g, const float* __restrict__ A2g,
    const float* __restrict__ b1g, const float* __restrict__ b2g,
    const float* __restrict__ bA2g,
    const float* __restrict__ A3g, const float* __restrict__ bA3g,
    const float* __restrict__ r2e,
    const int* __restrict__ pu_, const int* __restrict__ pr_)
{
    extern __shared__ char smraw[];
    SmemW& s = *(SmemW*)smraw;
    const int tid = threadIdx.x;

    build_w(W1g, s.Wt[0], s.Wt[1], tid);   // W1a (rows 0..63)
    build_w(W2g, s.Wt[2], s.Wt[3], tid);
    build_w(A1g, s.Wt[4], s.Wt[5], tid);   // A1a (rows 0..63)
    build_w(A2g, s.Wt[6], s.Wt[7], tid);
    if (tid < 64) {
        s.cb[tid] = b2g[tid];
        s.cb[64 + tid] = bA2g[tid];
        s.cb[128 + tid] = A3g[tid];
    }
    // rbias[rr][f] = b1[f] + r2e[rr] . W1[64:128][:,f]  (exact fp32, in-kernel)
    if (tid < NRAT * 64) {
        int rr = tid >> 6, f = tid & 63;
        float a = b1g[f];
        #pragma unroll 8
        for (int k = 0; k < 64; ++k)
            a = fmaf(r2e[rr * 64 + k], W1g[(64 + k) * 64 + f], a);
        s.rbias[rr * RBL + f] = a;
    }
    const float bA3 = bA3g[0];
    __syncthreads();

    const int hf = tid >> 8, htid = tid & 255;
    HalfW& h = s.h[hf];
    const int hwarp = htid >> 5, rw = hwarp >> 1, cw = hwarp & 1;

    const int total = g_count;
    const int ntiles = (total + 63) >> 6;
    const int tstep = gridDim.x * 2;
    FragC acc[2];

    int t = blockIdx.x * 2 + hf;
    int ib = 0, par = 0;

    // prologue: idx + u-gather for first tile
    if (t < ntiles) {
        if (htid < 64) {
            int e = (t << 6) + htid;
            int pair = (e < total) ? g_pairs[e] : 0;
            int n = pair >> 6, l = pair & 63;
            h.idx[0][0][htid] = n; h.idx[0][1][htid] = l;
            h.idx[0][2][htid] = pu_[n * LL + l];
            h.idx[0][3][htid] = pr_[n * LL + l];
        }
        barh(hf);
        for (int v = htid; v < 64 * 8; v += 256) {
            int m = v >> 3, c = v & 7;
            int ui = h.idx[0][2][m];
            cp16(h.pu[0][0] + m * PLD + c * 8, g_u2e_h + (size_t)ui * 64 + c * 8);
            cp16(h.pu[0][1] + m * PLD + c * 8, g_u2e_l + (size_t)ui * 64 + c * 8);
        }
        cp_commit();
    }

    for (; t < ntiles; t += tstep, ib ^= 1, par ^= 1) {
        const int* pn  = h.idx[ib][0];
        const int* pl  = h.idx[ib][1];
        const int* rix = h.idx[ib][3];
        __nv_bfloat16* Ph = h.pu[par][0];
        __nv_bfloat16* Pl = h.pu[par][1];

        // issue post_a1 gather (consumed at a1-convert)
        for (int v = htid; v < 64 * 16; v += 256) {
            int m = v >> 4, c = v & 15;
            cp16(h.pstage + m * RBL + c * 4, g_post_a1 + (size_t)pn[m] * 64 + c * 4);
        }
        cp_commit();
        cp_wait1();   // u(cur) done; pstage still flying
        barh(hf);

        // L1: x = relu(u W1a + rbias[rix])
        ZERO_ACC();
        mma_stage_h(acc, Ph, Pl, s.Wt[0], s.Wt[1], rw, cw);
        store_convert_h<1>(h, acc, s.rbias, rix, Ph, Pl, rw, cw, htid, hf, false, pn, pl);

        // L2: o = relu(x W2 + b2) ; STG fp32 to g_o
        ZERO_ACC();
        mma_stage_h(acc, Ph, Pl, s.Wt[2], s.Wt[3], rw, cw);
        store_convert_h<0>(h, acc, s.cb, nullptr, Ph, Pl, rw, cw, htid, hf, true, pn, pl);

        // L3: a1 = relu(o A1a + post_a1[pn])
        ZERO_ACC();
        mma_stage_h(acc, Ph, Pl, s.Wt[4], s.Wt[5], rw, cw);
        cp_wait0();   // pstage arrived
        store_convert_h<2>(h, acc, h.pstage, nullptr, Ph, Pl, rw, cw, htid, hf, false, pn, pl);

        // load next tile's indices (overlaps L4)
        int tn = t + tstep;
        if (htid < 64) {
            int e = (tn << 6) + htid;
            int pair = (tn < ntiles && e < total) ? g_pairs[e] : 0;
            int n = pair >> 6, l = pair & 63;
            h.idx[ib ^ 1][0][htid] = n; h.idx[ib ^ 1][1][htid] = l;
            h.idx[ib ^ 1][2][htid] = pu_[n * LL + l];
            h.idx[ib ^ 1][3][htid] = pr_[n * LL + l];
        }

        // L4: a2 = a1 A2 (relu folded into logit pass)
        ZERO_ACC();
        mma_stage_h(acc, Ph, Pl, s.Wt[6], s.Wt[7], rw, cw);
        #pragma unroll
        for (int c = 0; c < 2; ++c)
            wmma::store_matrix_sync(h.scratch + (rw * 16) * SLD + cw * 32 + c * 16,
                                    acc[c], SLD, wmma::mem_row_major);
        barh(hf);   // scratch ready; idx[ib^1] visible; planes free

        // prefetch next tile's u into the other parity planes
        if (tn < ntiles) {
            for (int v = htid; v < 64 * 8; v += 256) {
                int m = v >> 3, c = v & 7;
                int ui = h.idx[ib ^ 1][2][m];
                cp16(h.pu[par ^ 1][0] + m * PLD + c * 8, g_u2e_h + (size_t)ui * 64 + c * 8);
                cp16(h.pu[par ^ 1][1] + m * PLD + c * 8, g_u2e_l + (size_t)ui * 64 + c * 8);
            }
            cp_commit();
        }

        // logit = relu(a2 + bA2) . A3 + bA3  (4 threads per item)
        {
            int m = htid >> 2, c0 = (htid & 3) << 4;
            const float* src = h.scratch + m * SLD + c0;
            float lg = 0.f;
            #pragma unroll 4
            for (int j = 0; j < 16; ++j) {
                float v = fmaxf(src[j] + s.cb[64 + c0 + j], 0.f);
                lg = fmaf(v, s.cb[128 + c0 + j], lg);
            }
            lg += __shfl_xor_sync(0xffffffffu, lg, 1);
            lg += __shfl_xor_sync(0xffffffffu, lg, 2);
            if ((htid & 3) == 0)
                g_logits[pn[m] * LL + pl[m]] = lg + bA3;
        }
        barh(hf);   // protect scratch/idx before next tile
    }
}

// ---------------- finalize (fp32, proven) ----------------
struct SmemFin {
    float Ow[128 * 64];
    float bOw[64];
    float att[8][64];
    float in[8][128];
    float red[8][4][64];
};

__global__ void __launch_bounds__(512, 1) k_fin(
    const float* __restrict__ Owg, const float* __restrict__ bOwg,
    const int* __restrict__ lengths, float* __restrict__ out)
{
    extern __shared__ float smem_raw[];
    SmemFin& s = *(SmemFin*)smem_raw;
    int tid = threadIdx.x;
    for (int i = tid; i < 128 * 64; i += 512) s.Ow[i] = Owg[i];
    if (tid < 64) s.bOw[tid] = bOwg[tid];
    __syncthreads();

    const int g = tid >> 6;
    const int gt = tid & 63;

    for (int base = blockIdx.x * 8; base < NN; base += gridDim.x * 8) {
        int n = base + g;
        int len = lengths[n];

        if (gt < 32) {
            int lane = gt;
            float l0 = (lane < len)      ? g_logits[n * LL + lane]      : -INFINITY;
            float l1 = (lane + 32 < len) ? g_logits[n * LL + lane + 32] : -INFINITY;
            float m = fmaxf(l0, l1);
            #pragma unroll
            for (int off = 16; off >= 1; off >>= 1)
                m = fmaxf(m, __shfl_xor_sync(0xffffffffu, m, off));
            float e0 = (lane < len)      ? expf(l0 - m) : 0.f;
            float e1 = (lane + 32 < len) ? expf(l1 - m) : 0.f;
            float sum = e0 + e1;
            #pragma unroll
            for (int off = 16; off >= 1; off >>= 1)
                sum += __shfl_xor_sync(0xffffffffu, sum, off);
            float inv = 1.f / sum;
            s.att[g][lane] = e0 * inv; s.att[g][lane + 32] = e1 * inv;
        } else {
            int f0 = gt - 32;
            s.in[g][64 + f0]      = g_post[n * 64 + f0];
            s.in[g][64 + f0 + 32] = g_post[n * 64 + f0 + 32];
        }
        __syncthreads();

        {
            const float* orow = g_o + (size_t)n * LL * 64 + gt;
            float h0 = 0.f, h1 = 0.f, h2 = 0.f, h3 = 0.f;
            int l = 0;
            for (; l + 3 < len; l += 4) {
                h0 = fmaf(s.att[g][l],     orow[(size_t)(l)     * 64], h0);
                h1 = fmaf(s.att[g][l + 1], orow[(size_t)(l + 1) * 64], h1);
                h2 = fmaf(s.att[g][l + 2], orow[(size_t)(l + 2) * 64], h2);
                h3 = fmaf(s.att[g][l + 3], orow[(size_t)(l + 3) * 64], h3);
            }
            for (; l < len; ++l)
                h0 = fmaf(s.att[g][l], orow[(size_t)l * 64], h0);
            s.in[g][gt] = (h0 + h1) + (h2 + h3);
        }
        __syncthreads();

        {
            int fslot = gt & 15, kslot = gt >> 4;
            float4 acc2 = make_float4(0.f, 0.f, 0.f, 0.f);
            const float* Wp = s.Ow + fslot * 4;
            #pragma unroll 8
            for (int k = kslot * 32; k < kslot * 32 + 32; ++k) {
                float xv = s.in[g][k];
                float4 w = *(const float4*)(Wp + k * 64);
                acc2.x = fmaf(xv, w.x, acc2.x); acc2.y = fmaf(xv, w.y, acc2.y);
                acc2.z = fmaf(xv, w.z, acc2.z); acc2.w = fmaf(xv, w.w, acc2.w);
            }
            *(float4*)(&s.red[g][kslot][fslot * 4]) = acc2;
        }
        __syncthreads();

        {
            float v = s.bOw[gt] + s.red[g][0][gt] + s.red[g][1][gt]
                                + s.red[g][2][gt] + s.red[g][3][gt];
            out[n * 64 + gt] = fmaxf(v, 0.f);
        }
        __syncthreads();
    }
}

// ---------------- launch ----------------
extern "C" void kernel_launch(void* const* d_in, const int* in_sizes, int n_in,
                              void* d_out, int out_size)
{
    const float* u2e     = (const float*)d_in[0];
    const float* r2e     = (const float*)d_in[1];
    const float* content = (const float*)d_in[2];
    const float* We_w = (const float*)d_in[3];  const float* We_b = (const float*)d_in[4];
    const float* W1_w = (const float*)d_in[5];  const float* W1_b = (const float*)d_in[6];
    const float* W2_w = (const float*)d_in[7];  const float* W2_b = (const float*)d_in[8];
    const float* A1_w = (const float*)d_in[9];  const float* A1_b = (const float*)d_in[10];
    const float* A2_w = (const float*)d_in[11]; const float* A2_b = (const float*)d_in[12];
    const float* A3_w = (const float*)d_in[13]; const float* A3_b = (const float*)d_in[14];
    const float* Ow_w = (const float*)d_in[15]; const float* Ow_b = (const float*)d_in[16];
    const int* pu      = (const int*)d_in[18];
    const int* pr      = (const int*)d_in[19];
    const int* lengths = (const int*)d_in[20];
    const int* prc     = (const int*)d_in[21];
    float* out = (float*)d_out;

    static int nsm = 0;
    if (nsm == 0) {
        cudaDeviceGetAttribute(&nsm, cudaDevAttrMultiProcessorCount, 0);
        cudaFuncSetAttribute(k_main_w, cudaFuncAttributeMaxDynamicSharedMemorySize, (int)sizeof(SmemW));
        cudaFuncSetAttribute(k_post, cudaFuncAttributeMaxDynamicSharedMemorySize, (int)sizeof(SmemPost));
        cudaFuncSetAttribute(k_fin,  cudaFuncAttributeMaxDynamicSharedMemorySize, (int)sizeof(SmemFin));
    }

    k_reset<<<1, 1>>>();
    k_build_pairs<<<NN / 256, 256>>>(lengths);
    k_pack_emb<<<(NUSERS * EE + 511) / 512, 512>>>(u2e);
    k_post<<<NN / 64, 256, sizeof(SmemPost)>>>(content, We_w, We_b, prc, A1_w, A1_b);
    k_main_w<<<nsm, 512, sizeof(SmemW)>>>(W1_w, W2_w, A1_w, A2_w,
                                          W1_b, W2_b, A2_b, A3_w, A3_b, r2e, pu, pr);
    k_fin<<<nsm, 512, sizeof(SmemFin)>>>(Ow_w, Ow_b, lengths, out);
}

// round 17
// speedup vs baseline: 1.1239x; 1.1239x over previous
#include <cuda_runtime.h>
#include <cuda_bf16.h>
#include <mma.h>
#include <cstdint>
#include <math.h>

#define NN 16384
#define LL 50
#define EE 64
#define CEDIM 128
#define NUSERS 100000
#define NRAT 6

typedef unsigned long long ull;
typedef unsigned int u32;

using namespace nvcuda;
typedef wmma::fragment<wmma::matrix_a, 16, 16, 16, __nv_bfloat16, wmma::row_major> FragA;
typedef wmma::fragment<wmma::matrix_b, 16, 16, 16, __nv_bfloat16, wmma::row_major> FragB;
typedef wmma::fragment<wmma::accumulator, 16, 16, 16, float> FragC;

// ---------------- device scratch ----------------
__device__ float g_post[NN * EE];                    // 4 MB
__device__ float g_post_a1[NN * EE];                 // 4 MB  (post @ A1b + bA1, fp32)
__device__ float g_o[(size_t)NN * LL * EE];          // 210 MB
__device__ float g_logits[NN * LL];                  // 3.3 MB
__device__ int   g_pairs[NN * LL];                   // 3.3 MB
__device__ int   g_count;
#define RBL 68
// packed hi/lo bf16 u table
__device__ __nv_bfloat16 g_u2e_h[NUSERS * EE];
__device__ __nv_bfloat16 g_u2e_l[NUSERS * EE];

__global__ void k_reset() { g_count = 0; }

__global__ void k_build_pairs(const int* __restrict__ lengths) {
    int n = blockIdx.x * blockDim.x + threadIdx.x;
    if (n >= NN) return;
    int len = lengths[n];
    int base = atomicAdd(&g_count, len);
    for (int l = 0; l < len; ++l) g_pairs[base + l] = (n << 6) | l;
}

__global__ void k_pack_emb(const float* __restrict__ u2e) {
    int i = blockIdx.x * blockDim.x + threadIdx.x;
    if (i < NUSERS * EE) {
        float x = u2e[i];
        __nv_bfloat16 h = __float2bfloat16(x);
        g_u2e_h[i] = h;
        g_u2e_l[i] = __float2bfloat16(x - __bfloat162float(h));
    }
}

// ---------------- helpers ----------------
__device__ __forceinline__ void ffma2(ull& d, ull a, ull b) {
    asm("fma.rn.f32x2 %0, %1, %2, %0;" : "+l"(d) : "l"(a), "l"(b));
}
__device__ __forceinline__ float hsum2(ull v) {
    float2 p = *(float2*)&v;
    return p.x + p.y;
}
__device__ __forceinline__ void cp16(void* dst, const void* src) {
    unsigned d = (unsigned)__cvta_generic_to_shared(dst);
    asm volatile("cp.async.cg.shared.global [%0], [%1], 16;" :: "r"(d), "l"(src));
}
__device__ __forceinline__ void cp_commit() {
    asm volatile("cp.async.commit_group;");
}
__device__ __forceinline__ void cp_wait0() {
    asm volatile("cp.async.wait_group 0;" ::: "memory");
}
__device__ __forceinline__ void cp_wait1() {
    asm volatile("cp.async.wait_group 1;" ::: "memory");
}
__device__ __forceinline__ void barh(int hf) {
    asm volatile("bar.sync %0, 128;" :: "r"(hf + 1) : "memory");
}
__device__ __forceinline__ u32 packbf(float x0, float x1) {
    u32 r;
    asm("cvt.rn.bf16x2.f32 %0, %1, %2;" : "=r"(r) : "f"(x1), "f"(x0));
    return r;
}

__device__ __forceinline__ void load_wt(const float* __restrict__ Wg, float* __restrict__ Wt,
                                        int K, int tid, int nthr) {
    for (int i = tid; i < K * 64; i += nthr) {
        int k = i >> 6, f = i & 63;
        Wt[(k >> 2) * 256 + ((f >> 2) + (f & 3) * 16) * 4 + (k & 3)] = Wg[i];
    }
}

#define MAP_SLOTS() \
    const int fslot = (((tid >> 5) & 3) << 2) + (tid & 3); \
    const int ibase = ((tid >> 7) << 5) + ((tid >> 2) & 7);

template<bool RELU>
__device__ __forceinline__ void tile_gemm_p(
    const float* __restrict__ Wt, const float* __restrict__ bias,
    const float* __restrict__ inA, int ldA, int K,
    float* __restrict__ out, int ldO, int tid)
{
    MAP_SLOTS();
    ull acc[4][4];
    #pragma unroll
    for (int j = 0; j < 4; ++j)
        #pragma unroll
        for (int ff = 0; ff < 4; ++ff) acc[j][ff] = 0ull;

    const float* wp = Wt + fslot * 4;
    const float* xp = inA + ibase * ldA;
    const int nkb = K >> 2;
    #pragma unroll 4
    for (int kb = 0; kb < nkb; ++kb) {
        ulonglong2 w[4];
        #pragma unroll
        for (int ff = 0; ff < 4; ++ff)
            w[ff] = *(const ulonglong2*)(wp + kb * 256 + ff * 64);
        ulonglong2 x[4];
        #pragma unroll
        for (int j = 0; j < 4; ++j)
            x[j] = *(const ulonglong2*)(xp + j * (8 * ldA) + kb * 4);
        #pragma unroll
        for (int j = 0; j < 4; ++j)
            #pragma unroll
            for (int ff = 0; ff < 4; ++ff) {
                ffma2(acc[j][ff], x[j].x, w[ff].x);
                ffma2(acc[j][ff], x[j].y, w[ff].y);
            }
    }
    float4 b4 = ((const float4*)bias)[fslot];
    #pragma unroll
    for (int j = 0; j < 4; ++j) {
        float4 v;
        v.x = hsum2(acc[j][0]) + b4.x;
        v.y = hsum2(acc[j][1]) + b4.y;
        v.z = hsum2(acc[j][2]) + b4.z;
        v.w = hsum2(acc[j][3]) + b4.w;
        if (RELU) {
            v.x = fmaxf(v.x, 0.f); v.y = fmaxf(v.y, 0.f);
            v.z = fmaxf(v.z, 0.f); v.w = fmaxf(v.w, 0.f);
        }
        *(float4*)(out + (ibase + 8 * j) * ldO + fslot * 4) = v;
    }
}

// ---------------- post kernel: post + post_a1 in one launch ----------------
#define LDIN 132

struct SmemPost {
    float Wet[128 * 64];
    float Wa1b[64 * 64];
    float bWe[64], bA1v[64];
    float in[64 * LDIN];
    float postb[64 * RBL];
    int   cix[64];
};

__global__ void __launch_bounds__(256, 1) k_post(
    const float* __restrict__ content, const float* __restrict__ Weg,
    const float* __restrict__ bWeg, const int* __restrict__ pr_content,
    const float* __restrict__ A1g, const float* __restrict__ bA1g)
{
    extern __shared__ float smem_raw[];
    SmemPost& s = *(SmemPost*)smem_raw;
    int tid = threadIdx.x;
    load_wt(Weg, s.Wet, 128, tid, 256);
    load_wt(A1g + 64 * 64, s.Wa1b, 64, tid, 256);
    if (tid < 64) {
        s.bWe[tid] = bWeg[tid]; s.bA1v[tid] = bA1g[tid];
        s.cix[tid] = pr_content[blockIdx.x * 64 + tid];
    }
    __syncthreads();
    for (int v = tid; v < 64 * 32; v += 256) {
        int it = v >> 5, sub = v & 31;
        cp16(s.in + it * LDIN + sub * 4,
             content + (size_t)s.cix[it] * 128 + sub * 4);
    }
    cp_commit(); cp_wait0();
    __syncthreads();
    tile_gemm_p<true>(s.Wet, s.bWe, s.in, LDIN, 128, s.postb, RBL, tid);
    __syncthreads();
    for (int v = tid; v < 64 * 16; v += 256) {
        int it = v >> 4, sub = v & 15;
        ((float4*)(g_post + ((size_t)blockIdx.x * 64 + it) * 64))[sub] =
            *(const float4*)(s.postb + it * RBL + sub * 4);
    }
    tile_gemm_p<false>(s.Wa1b, s.bA1v, s.postb, RBL, 64,
                       g_post_a1 + (size_t)blockIdx.x * 64 * 64, 64, tid);
}

// ==================== WMMA main kernel: two 128-thread halves (R14 proven) ====
#define PLD 72   // bf16 plane stride (144B)
#define SLD 68   // fp32 scratch stride (272B)

struct HalfW {
    __nv_bfloat16 pu[2][2][64 * PLD];   // [parity][hi/lo]
    float pstage[64 * RBL];             // post_a1 rows (fp32)
    float scratch[64 * SLD];
    int idx[2][4][64];                  // [buf][pn,pl,uix,rix]
};
struct SmemW {
    HalfW h[2];
    __nv_bfloat16 Wt[8][64 * PLD];      // {W1a,W2,A1a,A2} x {hi,lo}
    float rbias[NRAT * RBL];
    float cb[3 * 64];                   // b2 | bA2 | A3
};

__device__ __forceinline__ void build_w(const float* __restrict__ Wg,
                                        __nv_bfloat16* wh, __nv_bfloat16* wl, int tid) {
    for (int i = tid; i < 64 * 64; i += 256) {
        int k = i >> 6, f = i & 63;
        float w = Wg[k * 64 + f];
        __nv_bfloat16 h = __float2bfloat16(w);
        wh[k * PLD + f] = h;
        wl[k * PLD + f] = __float2bfloat16(w - __bfloat162float(h));
    }
}

// one 64-K MMA stage for a 64x64 half-tile (32x32 warp tile): 3-term split
__device__ __forceinline__ void mma_stage_h(
    FragC acc[2][2],
    const __nv_bfloat16* Ah, const __nv_bfloat16* Al,
    const __nv_bfloat16* Bh, const __nv_bfloat16* Bl, int rw, int cw)
{
    #pragma unroll
    for (int kt = 0; kt < 4; ++kt) {
        FragA ah[2], al[2];
        #pragma unroll
        for (int r = 0; r < 2; ++r) {
            wmma::load_matrix_sync(ah[r], Ah + (rw * 32 + r * 16) * PLD + kt * 16, PLD);
            wmma::load_matrix_sync(al[r], Al + (rw * 32 + r * 16) * PLD + kt * 16, PLD);
        }
        #pragma unroll
        for (int c = 0; c < 2; ++c) {
            FragB bh, bl;
            wmma::load_matrix_sync(bh, Bh + kt * 16 * PLD + cw * 32 + c * 16, PLD);
            wmma::load_matrix_sync(bl, Bl + kt * 16 * PLD + cw * 32 + c * 16, PLD);
            #pragma unroll
            for (int r = 0; r < 2; ++r) {
                wmma::mma_sync(acc[r][c], ah[r], bh, acc[r][c]);
                wmma::mma_sync(acc[r][c], al[r], bh, acc[r][c]);
                wmma::mma_sync(acc[r][c], ah[r], bl, acc[r][c]);
            }
        }
    }
}

#define ZERO_ACC() do { \
    _Pragma("unroll") \
    for (int r = 0; r < 2; ++r) \
        _Pragma("unroll") \
        for (int c = 0; c < 2; ++c) wmma::fill_fragment(acc[r][c], 0.f); \
} while (0)

// BM: 0 = column bias; 1 = row bias rbias[rix[m]]; 2 = row bias pstage[m]
template<int BM>
__device__ __forceinline__ void store_convert_h(
    HalfW& h, FragC acc[2][2], const float* __restrict__ bias_c,
    const int* __restrict__ rix,
    __nv_bfloat16* dh, __nv_bfloat16* dl,
    int rw, int cw, int htid, int hf,
    bool og, const int* __restrict__ pn, const int* __restrict__ pl)
{
    #pragma unroll
    for (int r = 0; r < 2; ++r)
        #pragma unroll
        for (int c = 0; c < 2; ++c)
            wmma::store_matrix_sync(h.scratch + (rw * 32 + r * 16) * SLD + cw * 32 + c * 16,
                                    acc[r][c], SLD, wmma::mem_row_major);
    barh(hf);
    {
        int m = htid >> 1, c0 = (htid & 1) << 5;
        const float* src = h.scratch + m * SLD + c0;
        const float* bb;
        if (BM == 0)      bb = bias_c + c0;
        else if (BM == 1) bb = bias_c + rix[m] * RBL + c0;
        else              bb = bias_c + m * RBL + c0;
        float v[32];
        #pragma unroll
        for (int q = 0; q < 8; ++q) {
            float4 x = *(const float4*)(src + q * 4);
            float4 b = *(const float4*)(bb + q * 4);
            v[q * 4]     = fmaxf(x.x + b.x, 0.f);
            v[q * 4 + 1] = fmaxf(x.y + b.y, 0.f);
            v[q * 4 + 2] = fmaxf(x.z + b.z, 0.f);
            v[q * 4 + 3] = fmaxf(x.w + b.w, 0.f);
        }
        u32 hp[16], lp[16];
        #pragma unroll
        for (int e = 0; e < 16; ++e) {
            float x0 = v[2 * e], x1 = v[2 * e + 1];
            u32 hw = packbf(x0, x1);
            float h0 = __uint_as_float(hw << 16);
            float h1 = __uint_as_float(hw & 0xffff0000u);
            hp[e] = hw;
            lp[e] = packbf(x0 - h0, x1 - h1);
        }
        #pragma unroll
        for (int q = 0; q < 4; ++q) {
            *(uint4*)(dh + m * PLD + c0 + q * 8) =
                make_uint4(hp[q * 4], hp[q * 4 + 1], hp[q * 4 + 2], hp[q * 4 + 3]);
            *(uint4*)(dl + m * PLD + c0 + q * 8) =
                make_uint4(lp[q * 4], lp[q * 4 + 1], lp[q * 4 + 2], lp[q * 4 + 3]);
        }
        if (og) {
            float* orow = g_o + ((size_t)pn[m] * LL + pl[m]) * 64 + c0;
            #pragma unroll
            for (int q = 0; q < 8; ++q)
                *(float4*)(orow + q * 4) =
                    make_float4(v[q * 4], v[q * 4 + 1], v[q * 4 + 2], v[q * 4 + 3]);
        }
    }
    barh(hf);
}

__global__ void __launch_bounds__(256, 1) k_main_w(
    const float* __restrict__ W1g, const float* __restrict__ W2g,
    const float* __restrict__ A1g, const float* __restrict__ A2g,
    const float* __restrict__ b1g, const float* __restrict__ b2g,
    const float* __restrict__ bA2g,
    const float* __restrict__ A3g, const float* __restrict__ bA3g,
    const float* __restrict__ r2e,
    const int* __restrict__ pu_, const int* __restrict__ pr_)
{
    extern __shared__ char smraw[];
    SmemW& s = *(SmemW*)smraw;
    const int tid = threadIdx.x;

    build_w(W1g, s.Wt[0], s.Wt[1], tid);   // W1a (rows 0..63)
    build_w(W2g, s.Wt[2], s.Wt[3], tid);
    build_w(A1g, s.Wt[4], s.Wt[5], tid);   // A1a (rows 0..63)
    build_w(A2g, s.Wt[6], s.Wt[7], tid);
    if (tid < 64) {
        s.cb[tid] = b2g[tid];
        s.cb[64 + tid] = bA2g[tid];
        s.cb[128 + tid] = A3g[tid];
    }
    // rbias[rr][f] = b1[f] + r2e[rr] . W1[64:128][:,f]  (exact fp32, in prologue)
    for (int i = tid; i < NRAT * 64; i += 256) {
        int rr = i >> 6, f = i & 63;
        float a = b1g[f];
        #pragma unroll 8
        for (int k = 0; k < 64; ++k)
            a = fmaf(r2e[rr * 64 + k], W1g[(64 + k) * 64 + f], a);
        s.rbias[rr * RBL + f] = a;
    }
    const float bA3 = bA3g[0];
    __syncthreads();

    const int hf = tid >> 7, htid = tid & 127;
    HalfW& h = s.h[hf];
    const int hwarp = htid >> 5, rw = hwarp >> 1, cw = hwarp & 1;

    const int total = g_count;
    const int ntiles = (total + 63) >> 6;
    const int tstep = gridDim.x * 2;
    FragC acc[2][2];

    int t = blockIdx.x * 2 + hf;
    int ib = 0, par = 0;

    // prologue: idx + u-gather for first tile
    if (t < ntiles) {
        if (htid < 64) {
            int e = (t << 6) + htid;
            int pair = (e < total) ? g_pairs[e] : 0;
            int n = pair >> 6, l = pair & 63;
            h.idx[0][0][htid] = n; h.idx[0][1][htid] = l;
            h.idx[0][2][htid] = pu_[n * LL + l];
            h.idx[0][3][htid] = pr_[n * LL + l];
        }
        barh(hf);
        for (int v = htid; v < 64 * 8; v += 128) {
            int m = v >> 3, c = v & 7;
            int ui = h.idx[0][2][m];
            cp16(h.pu[0][0] + m * PLD + c * 8, g_u2e_h + (size_t)ui * 64 + c * 8);
            cp16(h.pu[0][1] + m * PLD + c * 8, g_u2e_l + (size_t)ui * 64 + c * 8);
        }
        cp_commit();
    }

    for (; t < ntiles; t += tstep, ib ^= 1, par ^= 1) {
        const int* pn  = h.idx[ib][0];
        const int* pl  = h.idx[ib][1];
        const int* rix = h.idx[ib][3];
        __nv_bfloat16* Ph = h.pu[par][0];
        __nv_bfloat16* Pl = h.pu[par][1];

        // issue post_a1 gather (consumed at a1-convert)
        for (int v = htid; v < 64 * 16; v += 128) {
            int m = v >> 4, c = v & 15;
            cp16(h.pstage + m * RBL + c * 4, g_post_a1 + (size_t)pn[m] * 64 + c * 4);
        }
        cp_commit();
        cp_wait1();   // u(cur) done; pstage still flying
        barh(hf);

        // L1: x = relu(u W1a + rbias[rix])
        ZERO_ACC();
        mma_stage_h(acc, Ph, Pl, s.Wt[0], s.Wt[1], rw, cw);
        store_convert_h<1>(h, acc, s.rbias, rix, Ph, Pl, rw, cw, htid, hf, false, pn, pl);

        // L2: o = relu(x W2 + b2) ; STG fp32 to g_o
        ZERO_ACC();
        mma_stage_h(acc, Ph, Pl, s.Wt[2], s.Wt[3], rw, cw);
        store_convert_h<0>(h, acc, s.cb, nullptr, Ph, Pl, rw, cw, htid, hf, true, pn, pl);

        // L3: a1 = relu(o A1a + post_a1[pn])
        ZERO_ACC();
        mma_stage_h(acc, Ph, Pl, s.Wt[4], s.Wt[5], rw, cw);
        cp_wait0();   // pstage arrived
        store_convert_h<2>(h, acc, h.pstage, nullptr, Ph, Pl, rw, cw, htid, hf, false, pn, pl);

        // load next tile's indices (overlaps L4)
        int tn = t + tstep;
        if (htid < 64) {
            int e = (tn << 6) + htid;
            int pair = (tn < ntiles && e < total) ? g_pairs[e] : 0;
            int n = pair >> 6, l = pair & 63;
            h.idx[ib ^ 1][0][htid] = n; h.idx[ib ^ 1][1][htid] = l;
            h.idx[ib ^ 1][2][htid] = pu_[n * LL + l];
            h.idx[ib ^ 1][3][htid] = pr_[n * LL + l];
        }

        // L4: a2 = a1 A2 (relu folded into logit pass)
        ZERO_ACC();
        mma_stage_h(acc, Ph, Pl, s.Wt[6], s.Wt[7], rw, cw);
        #pragma unroll
        for (int r = 0; r < 2; ++r)
            #pragma unroll
            for (int c = 0; c < 2; ++c)
                wmma::store_matrix_sync(h.scratch + (rw * 32 + r * 16) * SLD + cw * 32 + c * 16,
                                        acc[r][c], SLD, wmma::mem_row_major);
        barh(hf);   // scratch ready; idx[ib^1] visible; planes free

        // prefetch next tile's u into the other parity planes
        if (tn < ntiles) {
            for (int v = htid; v < 64 * 8; v += 128) {
                int m = v >> 3, c = v & 7;
                int ui = h.idx[ib ^ 1][2][m];
                cp16(h.pu[par ^ 1][0] + m * PLD + c * 8, g_u2e_h + (size_t)ui * 64 + c * 8);
                cp16(h.pu[par ^ 1][1] + m * PLD + c * 8, g_u2e_l + (size_t)ui * 64 + c * 8);
            }
            cp_commit();
        }

        // logit = relu(a2 + bA2) . A3 + bA3
        {
            int m = htid >> 1, c0 = (htid & 1) << 5;
            const float* src = h.scratch + m * SLD + c0;
            float lg = 0.f;
            #pragma unroll 8
            for (int j = 0; j < 32; ++j) {
                float v = fmaxf(src[j] + s.cb[64 + c0 + j], 0.f);
                lg = fmaf(v, s.cb[128 + c0 + j], lg);
            }
            lg += __shfl_xor_sync(0xffffffffu, lg, 1);
            if ((htid & 1) == 0)
                g_logits[pn[m] * LL + pl[m]] = lg + bA3;
        }
        barh(hf);   // protect scratch/idx before next tile
    }
}

// ---------------- finalize (fp32, proven; 2 CTAs/SM) ----------------
struct SmemFin {
    float Ow[128 * 64];
    float bOw[64];
    float att[8][64];
    float in[8][128];
    float red[8][4][64];
};

__global__ void __launch_bounds__(512, 2) k_fin(
    const float* __restrict__ Owg, const float* __restrict__ bOwg,
    const int* __restrict__ lengths, float* __restrict__ out)
{
    extern __shared__ float smem_raw[];
    SmemFin& s = *(SmemFin*)smem_raw;
    int tid = threadIdx.x;
    for (int i = tid; i < 128 * 64; i += 512) s.Ow[i] = Owg[i];
    if (tid < 64) s.bOw[tid] = bOwg[tid];
    __syncthreads();

    const int g = tid >> 6;
    const int gt = tid & 63;

    for (int base = blockIdx.x * 8; base < NN; base += gridDim.x * 8) {
        int n = base + g;
        int len = lengths[n];

        if (gt < 32) {
            int lane = gt;
            float l0 = (lane < len)      ? g_logits[n * LL + lane]      : -INFINITY;
            float l1 = (lane + 32 < len) ? g_logits[n * LL + lane + 32] : -INFINITY;
            float m = fmaxf(l0, l1);
            #pragma unroll
            for (int off = 16; off >= 1; off >>= 1)
                m = fmaxf(m, __shfl_xor_sync(0xffffffffu, m, off));
            float e0 = (lane < len)      ? expf(l0 - m) : 0.f;
            float e1 = (lane + 32 < len) ? expf(l1 - m) : 0.f;
            float sum = e0 + e1;
            #pragma unroll
            for (int off = 16; off >= 1; off >>= 1)
                sum += __shfl_xor_sync(0xffffffffu, sum, off);
            float inv = 1.f / sum;
            s.att[g][lane] = e0 * inv; s.att[g][lane + 32] = e1 * inv;
        } else {
            int f0 = gt - 32;
            s.in[g][64 + f0]      = g_post[n * 64 + f0];
            s.in[g][64 + f0 + 32] = g_post[n * 64 + f0 + 32];
        }
        __syncthreads();

        {
            const float* orow = g_o + (size_t)n * LL * 64 + gt;
            float h0 = 0.f, h1 = 0.f, h2 = 0.f, h3 = 0.f;
            int l = 0;
            for (; l + 3 < len; l += 4) {
                h0 = fmaf(s.att[g][l],     orow[(size_t)(l)     * 64], h0);
                h1 = fmaf(s.att[g][l + 1], orow[(size_t)(l + 1) * 64], h1);
                h2 = fmaf(s.att[g][l + 2], orow[(size_t)(l + 2) * 64], h2);
                h3 = fmaf(s.att[g][l + 3], orow[(size_t)(l + 3) * 64], h3);
            }
            for (; l < len; ++l)
                h0 = fmaf(s.att[g][l], orow[(size_t)l * 64], h0);
            s.in[g][gt] = (h0 + h1) + (h2 + h3);
        }
        __syncthreads();

        {
            int fslot = gt & 15, kslot = gt >> 4;
            float4 acc2 = make_float4(0.f, 0.f, 0.f, 0.f);
            const float* Wp = s.Ow + fslot * 4;
            #pragma unroll 8
            for (int k = kslot * 32; k < kslot * 32 + 32; ++k) {
                float xv = s.in[g][k];
                float4 w = *(const float4*)(Wp + k * 64);
                acc2.x = fmaf(xv, w.x, acc2.x); acc2.y = fmaf(xv, w.y, acc2.y);
                acc2.z = fmaf(xv, w.z, acc2.z); acc2.w = fmaf(xv, w.w, acc2.w);
            }
            *(float4*)(&s.red[g][kslot][fslot * 4]) = acc2;
        }
        __syncthreads();

        {
            float v = s.bOw[gt] + s.red[g][0][gt] + s.red[g][1][gt]
                                + s.red[g][2][gt] + s.red[g][3][gt];
            out[n * 64 + gt] = fmaxf(v, 0.f);
        }
        __syncthreads();
    }
}

// ---------------- launch ----------------
extern "C" void kernel_launch(void* const* d_in, const int* in_sizes, int n_in,
                              void* d_out, int out_size)
{
    const float* u2e     = (const float*)d_in[0];
    const float* r2e     = (const float*)d_in[1];
    const float* content = (const float*)d_in[2];
    const float* We_w = (const float*)d_in[3];  const float* We_b = (const float*)d_in[4];
    const float* W1_w = (const float*)d_in[5];  const float* W1_b = (const float*)d_in[6];
    const float* W2_w = (const float*)d_in[7];  const float* W2_b = (const float*)d_in[8];
    const float* A1_w = (const float*)d_in[9];  const float* A1_b = (const float*)d_in[10];
    const float* A2_w = (const float*)d_in[11]; const float* A2_b = (const float*)d_in[12];
    const float* A3_w = (const float*)d_in[13]; const float* A3_b = (const float*)d_in[14];
    const float* Ow_w = (const float*)d_in[15]; const float* Ow_b = (const float*)d_in[16];
    const int* pu      = (const int*)d_in[18];
    const int* pr      = (const int*)d_in[19];
    const int* lengths = (const int*)d_in[20];
    const int* prc     = (const int*)d_in[21];
    float* out = (float*)d_out;

    static int nsm = 0;
    if (nsm == 0) {
        cudaDeviceGetAttribute(&nsm, cudaDevAttrMultiProcessorCount, 0);
        cudaFuncSetAttribute(k_main_w, cudaFuncAttributeMaxDynamicSharedMemorySize, (int)sizeof(SmemW));
        cudaFuncSetAttribute(k_post, cudaFuncAttributeMaxDynamicSharedMemorySize, (int)sizeof(SmemPost));
        cudaFuncSetAttribute(k_fin,  cudaFuncAttributeMaxDynamicSharedMemorySize, (int)sizeof(SmemFin));
    }

    k_reset<<<1, 1>>>();
    k_build_pairs<<<NN / 256, 256>>>(lengths);
    k_pack_emb<<<(NUSERS * EE + 511) / 512, 512>>>(u2e);
    k_post<<<NN / 64, 256, sizeof(SmemPost)>>>(content, We_w, We_b, prc, A1_w, A1_b);
    k_main_w<<<nsm, 256, sizeof(SmemW)>>>(W1_w, W2_w, A1_w, A2_w,
                                          W1_b, W2_b, A2_b, A3_w, A3_b, r2e, pu, pr);
    k_fin<<<nsm * 2, 512, sizeof(SmemFin)>>>(Ow_w, Ow_b, lengths, out);
}